// round 11
// baseline (speedup 1.0000x reference)
#include <cuda_runtime.h>
#include <cuda_fp16.h>
#include <stdint.h>

#define RES 512
#define PR  514           // padded resolution: 1-texel zero ring
#define CH  32
#define PLANE_PAD_ELEMS (PR * PR * CH)

// Zero-padded (H, W, C) fp16 planes. Texel = 32 halves = 64B.
// Interior texel (y, x) lives at padded coords (y+1, x+1).
__device__ __align__(128) __half g_TP[3][PLANE_PAD_ELEMS];

// ---------------------------------------------------------------------------
// Prep: transpose (C,H,W) fp32 -> padded (H,W,C) fp16, border-ring zeroing
// folded into the blockIdx.y==0 blocks. grid=(RES, RES/32, 3), block=(32,8).
// ---------------------------------------------------------------------------
__global__ __launch_bounds__(256) void triplane_prep_kernel(
    const float* __restrict__ t_xy,
    const float* __restrict__ t_yz,
    const float* __restrict__ t_zx)
{
    __shared__ float tile[32][33];   // [channel][x-in-tile]

    const int y  = blockIdx.x;
    const int x0 = blockIdx.y * 32;
    const int p  = blockIdx.z;
    const int tx = threadIdx.x;      // 0..31
    const int ty = threadIdx.y;      // 0..7
    const int tid = ty * 32 + tx;

    const float* src = (p == 0) ? t_xy : (p == 1) ? t_yz : t_zx;
    const float* sp = src + y * RES + x0 + tx;

#pragma unroll
    for (int i = 0; i < 4; ++i) {
        const int c = ty + 8 * i;
        tile[c][tx] = sp[c * (RES * RES)];   // coalesced, MLP=4
    }

    // Border zeroing: 2052 ring texels/plane spread over the 512 y-blocks.
    if (blockIdx.y == 0) {
        const int nt = (y == RES - 1) ? 32 : 16;
        if (tid < nt) {
            const int b   = 4 * y + (tid >> 2);   // ring texel index < 2052
            const int seg = tid & 3;
            int by, bx;
            if (b < PR)                 { by = 0;                    bx = b; }
            else if (b < 2 * PR)        { by = PR - 1;               bx = b - PR; }
            else if (b < 2 * PR + RES)  { by = b - 2 * PR + 1;       bx = 0; }
            else                        { by = b - (2 * PR + RES) + 1; bx = PR - 1; }
            *(uint4*)(g_TP[p] + ((size_t)by * PR + bx) * CH + seg * 8) =
                make_uint4(0u, 0u, 0u, 0u);
        }
    }
    __syncthreads();

    if (tid < 128) {
        const int xx  = tid >> 2;        // texel within tile (0..31)
        const int seg = tid & 3;         // 16B segment of the 64B texel

        uint4 v;
#pragma unroll
        for (int j = 0; j < 4; ++j) {
            const int c = seg * 8 + 2 * j;
            ((__half2*)&v)[j] = __floats2half2_rn(tile[c][xx], tile[c + 1][xx]);
        }
        *(uint4*)(g_TP[p] + ((size_t)(y + 1) * PR + (x0 + xx + 1)) * CH + seg * 8) = v;
    }
}

// ---------------------------------------------------------------------------
// Sampling: 8 lanes per point (xsel = s>>2 picks x corner, chunk = s&3 picks
// 8 channels). Padded planes -> no border math. All six plane loads issued
// back-to-back before any math. __launch_bounds__(256, 5) raises the reg cap
// to ~51 so ptxas can keep all 6 loads in flight (MLP=6) instead of
// re-serializing them to fit a 32-reg full-occupancy budget.
// ---------------------------------------------------------------------------
__global__ __launch_bounds__(256, 5) void triplane_sample_kernel(
    const float* __restrict__ xyz,
    float* __restrict__ out,
    int npts)
{
    const int gtid  = blockIdx.x * blockDim.x + threadIdx.x;
    const int pid   = gtid >> 3;
    const int s     = gtid & 7;
    const int chunk = s & 3;
    const int xsel  = s >> 2;

    // Warp-cooperative coord load: warp's 4 points need 12 floats (one line).
    const int lane = threadIdx.x & 31;
    const int wbase_pt = (blockIdx.x * blockDim.x + (threadIdx.x & ~31)) >> 3;
    float cv = 0.f;
    {
        const int ci = wbase_pt * 3 + lane;
        if (lane < 12 && ci < npts * 3) cv = __ldg(xyz + ci);
    }
    const int pg3 = (lane >> 3) * 3;
    const float cx = __shfl_sync(0xffffffffu, cv, pg3 + 0);
    const float cy = __shfl_sync(0xffffffffu, cv, pg3 + 1);
    const float cz = __shfl_sync(0xffffffffu, cv, pg3 + 2);

    if (pid >= npts) return;

    // f_xy: (X, Y)   f_yz: (Y, Z)   f_zx: (Z, X)
    const float cA[3] = {cx, cy, cz};   // W coordinate
    const float cB[3] = {cy, cz, cx};   // H coordinate

    const int laneoff = chunk * 8;      // this lane's 8-channel offset (halves)

    // --- Phase 1: all addresses + packed weights ---
    uint32_t off[3];
    __half2 w0h[3], w1h[3];
#pragma unroll
    for (int p = 0; p < 3; ++p) {
        // padded pixel coord = 256*c + 256.5; c in [-1,1) -> [0.5, 512.5):
        // floor indices in [0,512], no clamps, no masks.
        const float xf = fmaf(cA[p], 256.0f, 256.5f);
        const float yf = fmaf(cB[p], 256.0f, 256.5f);

        const float x0f = floorf(xf);
        const float y0f = floorf(yf);
        const float wx1 = xf - x0f;
        const float wy1 = yf - y0f;

        const int ixp = (int)x0f;
        const int iyp = (int)y0f;

        const float wxl = xsel ? wx1 : (1.0f - wx1);
        w0h[p] = __float2half2_rn((1.0f - wy1) * wxl);
        w1h[p] = __float2half2_rn(wy1 * wxl);
        off[p] = (uint32_t)(iyp * PR + ixp + xsel) * CH + laneoff;
    }

    // --- Phase 2: six back-to-back loads (MLP=6, now register-feasible) ---
    uint4 v0[3], v1[3];
#pragma unroll
    for (int p = 0; p < 3; ++p) {
        const __half* t = g_TP[p] + off[p];
        v0[p] = __ldg((const uint4*)t);
        v1[p] = __ldg((const uint4*)(t + PR * CH));
    }

    // --- Phase 3: math ---
    float acc[8];
#pragma unroll
    for (int j = 0; j < 8; ++j) acc[j] = 0.f;

#pragma unroll
    for (int p = 0; p < 3; ++p) {
        const __half2* h0 = (const __half2*)&v0[p];
        const __half2* h1 = (const __half2*)&v1[p];
#pragma unroll
        for (int j = 0; j < 4; ++j) {
            // per-plane bilinear partial in fp16: part = v0*w0 + v1*w1
            const __half2 part = __hfma2(h1[j], w1h[p], __hmul2(h0[j], w0h[p]));
            const float2 f = __half22float2(part);
            acc[2 * j]     += f.x;
            acc[2 * j + 1] += f.y;
        }
    }

    // Combine the two x-corner partial sums (lane s <-> lane s^4, same chunk).
#pragma unroll
    for (int k = 0; k < 8; ++k)
        acc[k] += __shfl_xor_sync(0xffffffffu, acc[k], 4);

    // xsel=0 stores floats 0-3 of the chunk, xsel=1 stores floats 4-7.
    const float4 o = xsel ? make_float4(acc[4], acc[5], acc[6], acc[7])
                          : make_float4(acc[0], acc[1], acc[2], acc[3]);
    *(float4*)(out + (size_t)pid * CH + chunk * 8 + xsel * 4) = o;
}

// ---------------------------------------------------------------------------
// kernel_launch
// inputs: xyz [N*3], T_xy, T_yz, T_zx [1*32*512*512] fp32 ; output [N*32] fp32
// ---------------------------------------------------------------------------
extern "C" void kernel_launch(void* const* d_in, const int* in_sizes, int n_in,
                              void* d_out, int out_size)
{
    const float* xyz  = (const float*)d_in[0];
    const float* t_xy = (const float*)d_in[1];
    const float* t_yz = (const float*)d_in[2];
    const float* t_zx = (const float*)d_in[3];
    float* out = (float*)d_out;

    const int npts = in_sizes[0] / 3;

    // 1) transpose + fp16 convert + border zeroing, one launch
    dim3 tgrid(RES, RES / 32, 3);
    dim3 tblock(32, 8);
    triplane_prep_kernel<<<tgrid, tblock>>>(t_xy, t_yz, t_zx);

    // 2) sample: 8 threads per point
    const long long total = (long long)npts * 8;
    const int block = 256;
    const int grid = (int)((total + block - 1) / block);
    triplane_sample_kernel<<<grid, block>>>(xyz, out, npts);
}

// round 12
// speedup vs baseline: 1.1262x; 1.1262x over previous
#include <cuda_runtime.h>
#include <cuda_fp16.h>
#include <stdint.h>

#define RES 512
#define PR  514           // padded resolution: 1-texel zero ring
#define CH  32
#define PLANE_PAD_ELEMS (PR * PR * CH)

// Zero-padded (H, W, C) fp16 planes. Texel = 32 halves = 64B.
// Interior texel (y, x) lives at padded coords (y+1, x+1).
__device__ __align__(128) __half g_TP[3][PLANE_PAD_ELEMS];

// ---------------------------------------------------------------------------
// Prep: transpose (C,H,W) fp32 -> padded (H,W,C) fp16, border-ring zeroing
// folded into the blockIdx.y==0 blocks. grid=(RES, RES/32, 3), block=(32,8).
// ---------------------------------------------------------------------------
__global__ __launch_bounds__(256) void triplane_prep_kernel(
    const float* __restrict__ t_xy,
    const float* __restrict__ t_yz,
    const float* __restrict__ t_zx)
{
    __shared__ float tile[32][33];   // [channel][x-in-tile]

    const int y  = blockIdx.x;
    const int x0 = blockIdx.y * 32;
    const int p  = blockIdx.z;
    const int tx = threadIdx.x;      // 0..31
    const int ty = threadIdx.y;      // 0..7
    const int tid = ty * 32 + tx;

    const float* src = (p == 0) ? t_xy : (p == 1) ? t_yz : t_zx;
    const float* sp = src + y * RES + x0 + tx;

#pragma unroll
    for (int i = 0; i < 4; ++i) {
        const int c = ty + 8 * i;
        tile[c][tx] = sp[c * (RES * RES)];   // coalesced, MLP=4
    }

    // Border zeroing: 2052 ring texels/plane spread over the 512 y-blocks.
    if (blockIdx.y == 0) {
        const int nt = (y == RES - 1) ? 32 : 16;
        if (tid < nt) {
            const int b   = 4 * y + (tid >> 2);   // ring texel index < 2052
            const int seg = tid & 3;
            int by, bx;
            if (b < PR)                 { by = 0;                    bx = b; }
            else if (b < 2 * PR)        { by = PR - 1;               bx = b - PR; }
            else if (b < 2 * PR + RES)  { by = b - 2 * PR + 1;       bx = 0; }
            else                        { by = b - (2 * PR + RES) + 1; bx = PR - 1; }
            *(uint4*)(g_TP[p] + ((size_t)by * PR + bx) * CH + seg * 8) =
                make_uint4(0u, 0u, 0u, 0u);
        }
    }
    __syncthreads();

    if (tid < 128) {
        const int xx  = tid >> 2;        // texel within tile (0..31)
        const int seg = tid & 3;         // 16B segment of the 64B texel

        uint4 v;
#pragma unroll
        for (int j = 0; j < 4; ++j) {
            const int c = seg * 8 + 2 * j;
            ((__half2*)&v)[j] = __floats2half2_rn(tile[c][xx], tile[c + 1][xx]);
        }
        *(uint4*)(g_TP[p] + ((size_t)(y + 1) * PR + (x0 + xx + 1)) * CH + seg * 8) = v;
    }
}

// ---------------------------------------------------------------------------
// Sampling: 8 lanes per point (xsel = s>>2 picks x corner, chunk = s&3 picks
// 8 channels). Padded planes -> no border math. Accumulation stays in half2
// END-TO-END (8 HFMA2 per plane per lane, no cvt, no fp32 adds); the
// x-corner combine is a half2 shfl + HADD2; fp32 conversion happens once at
// the store. R10 operating point: default launch bounds, ~28-32 regs, ~82% occ.
// ---------------------------------------------------------------------------
__global__ __launch_bounds__(256) void triplane_sample_kernel(
    const float* __restrict__ xyz,
    float* __restrict__ out,
    int npts)
{
    const int gtid  = blockIdx.x * blockDim.x + threadIdx.x;
    const int pid   = gtid >> 3;
    const int s     = gtid & 7;
    const int chunk = s & 3;
    const int xsel  = s >> 2;

    // Warp-cooperative coord load: warp's 4 points need 12 floats (one line).
    const int lane = threadIdx.x & 31;
    const int wbase_pt = (blockIdx.x * blockDim.x + (threadIdx.x & ~31)) >> 3;
    float cv = 0.f;
    {
        const int ci = wbase_pt * 3 + lane;
        if (lane < 12 && ci < npts * 3) cv = __ldg(xyz + ci);
    }
    const int pg3 = (lane >> 3) * 3;
    const float cx = __shfl_sync(0xffffffffu, cv, pg3 + 0);
    const float cy = __shfl_sync(0xffffffffu, cv, pg3 + 1);
    const float cz = __shfl_sync(0xffffffffu, cv, pg3 + 2);

    if (pid >= npts) return;

    // f_xy: (X, Y)   f_yz: (Y, Z)   f_zx: (Z, X)
    const float cA[3] = {cx, cy, cz};   // W coordinate
    const float cB[3] = {cy, cz, cx};   // H coordinate

    const int laneoff = chunk * 8;      // this lane's 8-channel offset (halves)

    // half2 accumulators for 8 channels
    __half2 acc[4];
    const __half2 hz = __float2half2_rn(0.f);
#pragma unroll
    for (int j = 0; j < 4; ++j) acc[j] = hz;

#pragma unroll
    for (int p = 0; p < 3; ++p) {
        // padded pixel coord = 256*c + 256.5; c in [-1,1) -> [0.5, 512.5):
        // floor indices in [0,512], no clamps, no masks.
        const float xf = fmaf(cA[p], 256.0f, 256.5f);
        const float yf = fmaf(cB[p], 256.0f, 256.5f);

        const float x0f = floorf(xf);
        const float y0f = floorf(yf);
        const float wx1 = xf - x0f;
        const float wy1 = yf - y0f;

        const int ixp = (int)x0f;
        const int iyp = (int)y0f;

        const float wxl = xsel ? wx1 : (1.0f - wx1);
        const __half2 w0h = __float2half2_rn((1.0f - wy1) * wxl);
        const __half2 w1h = __float2half2_rn(wy1 * wxl);

        const __half* t = g_TP[p]
                        + (size_t)(iyp * PR + ixp + xsel) * CH + laneoff;
        const uint4 v0 = __ldg((const uint4*)t);
        const uint4 v1 = __ldg((const uint4*)(t + PR * CH));

        const __half2* h0 = (const __half2*)&v0;
        const __half2* h1 = (const __half2*)&v1;
#pragma unroll
        for (int j = 0; j < 4; ++j) {
            acc[j] = __hfma2(h0[j], w0h, acc[j]);
            acc[j] = __hfma2(h1[j], w1h, acc[j]);
        }
    }

    // Combine the two x-corner partial sums (lane s <-> lane s^4) in half2.
#pragma unroll
    for (int j = 0; j < 4; ++j) {
        const uint32_t o = __shfl_xor_sync(0xffffffffu,
                                           *(const uint32_t*)&acc[j], 4);
        acc[j] = __hadd2(acc[j], *(const __half2*)&o);
    }

    // Convert to fp32 once and store. xsel=0 -> floats 0-3 of the chunk,
    // xsel=1 -> floats 4-7. Warp covers 512B contiguous.
    const float2 fa = __half22float2(acc[xsel ? 2 : 0]);
    const float2 fb = __half22float2(acc[xsel ? 3 : 1]);
    *(float4*)(out + (size_t)pid * CH + chunk * 8 + xsel * 4) =
        make_float4(fa.x, fa.y, fb.x, fb.y);
}

// ---------------------------------------------------------------------------
// kernel_launch
// inputs: xyz [N*3], T_xy, T_yz, T_zx [1*32*512*512] fp32 ; output [N*32] fp32
// ---------------------------------------------------------------------------
extern "C" void kernel_launch(void* const* d_in, const int* in_sizes, int n_in,
                              void* d_out, int out_size)
{
    const float* xyz  = (const float*)d_in[0];
    const float* t_xy = (const float*)d_in[1];
    const float* t_yz = (const float*)d_in[2];
    const float* t_zx = (const float*)d_in[3];
    float* out = (float*)d_out;

    const int npts = in_sizes[0] / 3;

    // 1) transpose + fp16 convert + border zeroing, one launch
    dim3 tgrid(RES, RES / 32, 3);
    dim3 tblock(32, 8);
    triplane_prep_kernel<<<tgrid, tblock>>>(t_xy, t_yz, t_zx);

    // 2) sample: 8 threads per point
    const long long total = (long long)npts * 8;
    const int block = 256;
    const int grid = (int)((total + block - 1) / block);
    triplane_sample_kernel<<<grid, block>>>(xyz, out, npts);
}